// round 1
// baseline (speedup 1.0000x reference)
#include <cuda_runtime.h>
#include <float.h>
#include <math.h>

// Problem constants (fixed shapes from reference: x = (4, 64, 64, 256) fp32)
#define BATCH 4
#define HW    4096          // 64*64 rows per batch
#define CDIM  256           // feature dim
#define BM    128           // row tile
#define BN    128           // col tile
#define BK    32            // k chunk
#define NTHREADS 256        // 16x16 threads, each 8x8 micro-tile
#define EPSQ  1e-9f
#define TLC   0.6f
#define LC    2.0f

// scratch: squared norms per row (allocated at module load, not in kernel_launch)
__device__ float g_norms[BATCH * HW];

// ---------------------------------------------------------------------------
// Kernel 1: row squared-norms. One warp per row.
// ---------------------------------------------------------------------------
__global__ void norms_kernel(const float* __restrict__ x) {
    int warp = (blockIdx.x * blockDim.x + threadIdx.x) >> 5;
    int lane = threadIdx.x & 31;
    if (warp >= BATCH * HW) return;
    const float4* row = (const float4*)(x + (size_t)warp * CDIM);
    float s = 0.f;
    #pragma unroll
    for (int k = lane; k < CDIM / 4; k += 32) {
        float4 v = row[k];
        s += v.x * v.x + v.y * v.y + v.z * v.z + v.w * v.w;
    }
    #pragma unroll
    for (int o = 16; o; o >>= 1) s += __shfl_xor_sync(0xffffffffu, s, o);
    if (lane == 0) g_norms[warp] = s;
}

// ---------------------------------------------------------------------------
// Kernel 2: fused  G-tile GEMM  ->  squared distance  ->  streaming top-2
// (off-diagonal) per row. Each block owns BM=128 rows of one batch and sweeps
// all 32 column tiles; running (min1, argmin1, min2) kept in shared memory.
// ---------------------------------------------------------------------------
__global__ __launch_bounds__(NTHREADS)
void fcm_kernel(const float* __restrict__ x, float* __restrict__ out, int out_size) {
    // GEMM staging (32 KB), aliased by the reduction scratch in the epilogue.
    __shared__ float sh[BK * BM + BK * BN];       // 8192 floats
    __shared__ float nBs[BN];
    __shared__ float s_m1[BM];
    __shared__ float s_m2[BM];
    __shared__ int   s_i1[BM];

    float* As   = sh;                 // [BK][BM], k-major
    float* Bs   = sh + BK * BM;       // [BK][BN], k-major
    float* r_m1 = sh;                 // epilogue alias: [16][BM]
    float* r_m2 = sh + 16 * BM;
    int*   r_i1 = (int*)(sh + 32 * BM);

    const int tid = threadIdx.x;
    const int tx  = tid & 15;         // col group (8 cols each)
    const int ty  = tid >> 4;         // row group (8 rows each)
    const int b    = blockIdx.y;
    const int row0 = blockIdx.x * BM;

    const float* X  = x + (size_t)b * HW * CDIM;
    const float* NB = g_norms + b * HW;

    if (tid < BM) { s_m1[tid] = FLT_MAX; s_m2[tid] = FLT_MAX; s_i1[tid] = 0; }

    // per-thread row norms are fixed for the whole block
    float nA[8];
    #pragma unroll
    for (int i = 0; i < 8; ++i) nA[i] = NB[row0 + ty * 8 + i];

    for (int jt = 0; jt < HW / BN; ++jt) {
        const int col0 = jt * BN;

        float acc[8][8];
        #pragma unroll
        for (int i = 0; i < 8; ++i)
            #pragma unroll
            for (int j = 0; j < 8; ++j) acc[i][j] = 0.f;

        __syncthreads();                       // previous epilogue done with sh/nBs
        if (tid < BN) nBs[tid] = NB[col0 + tid];

        for (int kc = 0; kc < CDIM; kc += BK) {
            if (kc) __syncthreads();           // previous chunk's FMAs done reading
            // stage A and B chunks (float4 along k, transposed store to k-major)
            #pragma unroll
            for (int l = 0; l < 4; ++l) {
                int lin = tid + l * NTHREADS;  // float4 id 0..1023
                int m   = lin >> 3;            // 0..127
                int k4  = lin & 7;             // 0..7
                float4 v = *(const float4*)(X + (size_t)(row0 + m) * CDIM + kc + k4 * 4);
                As[(k4 * 4 + 0) * BM + m] = v.x;
                As[(k4 * 4 + 1) * BM + m] = v.y;
                As[(k4 * 4 + 2) * BM + m] = v.z;
                As[(k4 * 4 + 3) * BM + m] = v.w;
                float4 w = *(const float4*)(X + (size_t)(col0 + m) * CDIM + kc + k4 * 4);
                Bs[(k4 * 4 + 0) * BN + m] = w.x;
                Bs[(k4 * 4 + 1) * BN + m] = w.y;
                Bs[(k4 * 4 + 2) * BN + m] = w.z;
                Bs[(k4 * 4 + 3) * BN + m] = w.w;
            }
            __syncthreads();

            #pragma unroll 8
            for (int k = 0; k < BK; ++k) {
                float a[8], bb[8];
                *(float4*)&a[0]  = *(const float4*)&As[k * BM + ty * 8];
                *(float4*)&a[4]  = *(const float4*)&As[k * BM + ty * 8 + 4];
                *(float4*)&bb[0] = *(const float4*)&Bs[k * BN + tx * 8];
                *(float4*)&bb[4] = *(const float4*)&Bs[k * BN + tx * 8 + 4];
                #pragma unroll
                for (int i = 0; i < 8; ++i)
                    #pragma unroll
                    for (int j = 0; j < 8; ++j)
                        acc[i][j] = fmaf(a[i], bb[j], acc[i][j]);
            }
        }
        __syncthreads();   // all FMAs done reading As/Bs before aliased reuse

        // ----- epilogue: squared distance + per-thread top-2 over 8 cols -----
        #pragma unroll
        for (int i = 0; i < 8; ++i) {
            const int r  = row0 + ty * 8 + i;
            const int rl = ty * 8 + i;
            float m1 = FLT_MAX, m2 = FLT_MAX;
            int   i1 = 0;
            #pragma unroll
            for (int j = 0; j < 8; ++j) {
                int   c = col0 + tx * 8 + j;
                float D = nA[i] + nBs[tx * 8 + j] - 2.f * acc[i][j];
                if (c != r) {                    // exclude diagonal (always global min)
                    if (D < m1) { m2 = m1; m1 = D; i1 = c; }
                    else if (D < m2) { m2 = D; }
                }
            }
            r_m1[tx * BM + rl] = m1;
            r_m2[tx * BM + rl] = m2;
            r_i1[tx * BM + rl] = i1;
        }
        __syncthreads();

        // merge the 16 column-group partials into the running per-row state
        if (tid < BM) {
            float m1 = s_m1[tid], m2 = s_m2[tid];
            int   i1 = s_i1[tid];
            #pragma unroll
            for (int t = 0; t < 16; ++t) {
                float bm1 = r_m1[t * BM + tid];
                float bm2 = r_m2[t * BM + tid];
                int   bi1 = r_i1[t * BM + tid];
                if (bm1 < m1) { m2 = fminf(m1, bm2); i1 = bi1; m1 = bm1; }
                else          { m2 = fminf(m2, bm1); }
            }
            s_m1[tid] = m1; s_m2[tid] = m2; s_i1[tid] = i1;
        }
    }

    __syncthreads();
    if (tid < BM) {
        // reference: D=relu(D)+eps; norms=sqrt(D); d1=2nd smallest, d2=3rd smallest
        float d1 = sqrtf(fmaxf(s_m1[tid], 0.f) + EPSQ);
        float d2 = sqrtf(fmaxf(s_m2[tid], 0.f) + EPSQ);
        float e  = expf(d1);
        float pred = (d1 / d2 < TLC) ? 2.f / (1.f + e) : 2.f / (1.f + LC * e);
        int r = row0 + tid;
        out[(size_t)b * HW + r] = pred;
        if (out_size >= 2 * BATCH * HW)
            out[(size_t)BATCH * HW + (size_t)b * HW + r] = (float)s_i1[tid];
    }
}

// ---------------------------------------------------------------------------
extern "C" void kernel_launch(void* const* d_in, const int* in_sizes, int n_in,
                              void* d_out, int out_size) {
    const float* x  = (const float*)d_in[0];
    float*       out = (float*)d_out;

    // 16384 rows, one warp each -> 2048 blocks of 256 threads
    norms_kernel<<<(BATCH * HW * 32 + NTHREADS - 1) / NTHREADS, NTHREADS>>>(x);

    dim3 grid(HW / BM, BATCH);
    fcm_kernel<<<grid, NTHREADS>>>(x, out, out_size);
}

// round 3
// speedup vs baseline: 2.9882x; 2.9882x over previous
#include <cuda_runtime.h>
#include <cuda_bf16.h>
#include <cstdint>
#include <float.h>
#include <math.h>

#define BATCH 4
#define HW    4096
#define CDIM  256
#define BM    128
#define BN    128
#define NTILES 32
#define NTHREADS 512
#define EPSQ  1e-9f
#define TLC   0.6f
#define LC    2.0f
#define SROWB 144           // padded SMEM row stride: 64 bf16 = 128B data + 16B pad
#define ABYTES (8 * 128 * SROWB)   // 147456: [hi|lo] x 4 k-chunks x 128 rows
#define BBYTES (128 * SROWB)       // 18432 per buffer
#define TOTSMEM (ABYTES + 2 * BBYTES)

// hi/lo bf16 split of x + fp32 row squared-norms (static scratch, no allocs)
__device__ __nv_bfloat16 g_xhi[BATCH * HW * CDIM];
__device__ __nv_bfloat16 g_xlo[BATCH * HW * CDIM];
__device__ float         g_norms[BATCH * HW];

// ---------------------------------------------------------------------------
__device__ __forceinline__ uint32_t smem_u32(const void* p) {
    uint32_t a;
    asm("{ .reg .u64 t; cvta.to.shared.u64 t, %1; cvt.u32.u64 %0, t; }"
        : "=r"(a) : "l"(p));
    return a;
}
__device__ __forceinline__ void cp16(uint32_t dst, const void* src) {
    asm volatile("cp.async.cg.shared.global [%0], [%1], 16;" :: "r"(dst), "l"(src));
}
__device__ __forceinline__ void cp_commit() {
    asm volatile("cp.async.commit_group;" ::: "memory");
}
template <int N> __device__ __forceinline__ void cp_wait() {
    asm volatile("cp.async.wait_group %0;" :: "n"(N) : "memory");
}
__device__ __forceinline__ void ldsm_x4(uint32_t (&r)[4], uint32_t addr) {
    asm volatile("ldmatrix.sync.aligned.m8n8.x4.shared.b16 {%0,%1,%2,%3}, [%4];"
                 : "=r"(r[0]), "=r"(r[1]), "=r"(r[2]), "=r"(r[3]) : "r"(addr));
}
#define MMA16816(d, a, b0_, b1_)                                                 \
    asm volatile("mma.sync.aligned.m16n8k16.row.col.f32.bf16.bf16.f32 "          \
                 "{%0,%1,%2,%3}, {%4,%5,%6,%7}, {%8,%9}, {%0,%1,%2,%3};"         \
                 : "+f"((d)[0]), "+f"((d)[1]), "+f"((d)[2]), "+f"((d)[3])        \
                 : "r"((a)[0]), "r"((a)[1]), "r"((a)[2]), "r"((a)[3]),           \
                   "r"(b0_), "r"(b1_))

// ---------------------------------------------------------------------------
// Kernel 1: hi/lo bf16 split (4 floats per thread)
// ---------------------------------------------------------------------------
__global__ void convert_kernel(const float* __restrict__ x) {
    int i = blockIdx.x * blockDim.x + threadIdx.x;
    float4 v = ((const float4*)x)[i];
    __nv_bfloat16 h0 = __float2bfloat16(v.x), h1 = __float2bfloat16(v.y);
    __nv_bfloat16 h2 = __float2bfloat16(v.z), h3 = __float2bfloat16(v.w);
    __nv_bfloat16 l0 = __float2bfloat16(v.x - __bfloat162float(h0));
    __nv_bfloat16 l1 = __float2bfloat16(v.y - __bfloat162float(h1));
    __nv_bfloat16 l2 = __float2bfloat16(v.z - __bfloat162float(h2));
    __nv_bfloat16 l3 = __float2bfloat16(v.w - __bfloat162float(h3));
    ((__nv_bfloat162*)g_xhi)[2 * i + 0] = __nv_bfloat162(h0, h1);
    ((__nv_bfloat162*)g_xhi)[2 * i + 1] = __nv_bfloat162(h2, h3);
    ((__nv_bfloat162*)g_xlo)[2 * i + 0] = __nv_bfloat162(l0, l1);
    ((__nv_bfloat162*)g_xlo)[2 * i + 1] = __nv_bfloat162(l2, l3);
}

// ---------------------------------------------------------------------------
// Kernel 2: fp32 row squared-norms (one warp per row)
// ---------------------------------------------------------------------------
__global__ void norms_kernel(const float* __restrict__ x) {
    int warp = (blockIdx.x * blockDim.x + threadIdx.x) >> 5;
    int lane = threadIdx.x & 31;
    if (warp >= BATCH * HW) return;
    const float4* row = (const float4*)(x + (size_t)warp * CDIM);
    float s = 0.f;
    #pragma unroll
    for (int k = lane; k < CDIM / 4; k += 32) {
        float4 v = row[k];
        s += v.x * v.x + v.y * v.y + v.z * v.z + v.w * v.w;
    }
    #pragma unroll
    for (int o = 16; o; o >>= 1) s += __shfl_xor_sync(0xffffffffu, s, o);
    if (lane == 0) g_norms[warp] = s;
}

// ---------------------------------------------------------------------------
// Kernel 3: HMMA Gram (hi*hi + lo*hi + hi*lo) + fused distance + streaming
// top-2/argmin. A (hi+lo) staged once in SMEM; B streams in 64-k chunks.
// ---------------------------------------------------------------------------
__global__ __launch_bounds__(NTHREADS, 1)
void fcm_mma_kernel(float* __restrict__ out, int out_size) {
    extern __shared__ __align__(16) char smem[];
    const uint32_t sbase = smem_u32(smem);
    const uint32_t aoff  = sbase;
    const uint32_t boff  = sbase + ABYTES;

    const int tid  = threadIdx.x;
    const int lane = tid & 31;
    const int w    = tid >> 5;
    const int mw   = w >> 2;          // 0..3 (M group of 32 rows)
    const int nw   = w & 3;           // 0..3 (N group of 32 cols)
    const int b    = blockIdx.y;
    const int row0 = blockIdx.x * BM;

    const __nv_bfloat16* xhi = g_xhi + (size_t)b * HW * CDIM;
    const __nv_bfloat16* xlo = g_xlo + (size_t)b * HW * CDIM;

    // ldmatrix per-lane address pieces
    const int lrow = ((lane >> 3) & 1) * 8 + (lane & 7);
    const int lkb  = (lane >> 4) * 16;   // bytes

    // ---- stage A: [hi|lo] x 4 k-chunks of 128x64, padded rows ----
    #pragma unroll
    for (int s = 0; s < 2; ++s) {
        const __nv_bfloat16* src = s ? xlo : xhi;
        #pragma unroll
        for (int kc = 0; kc < 4; ++kc) {
            #pragma unroll
            for (int o = 0; o < 2; ++o) {
                int lin = tid + o * NTHREADS;          // 0..1023
                int r = lin >> 3, gg = lin & 7;
                const void* sp = src + (size_t)(row0 + r) * CDIM + kc * 64 + gg * 8;
                cp16(aoff + (uint32_t)(((s * 4 + kc) * 128 + r) * SROWB + gg * 16), sp);
            }
        }
    }

    auto prefetch = [&](int g) {
        int jt = g >> 3, c = g & 7;
        const __nv_bfloat16* src = (c < 4) ? xhi : xlo;
        int kc = (c & 3) * 64, col0 = jt * BN;
        uint32_t dst = boff + (uint32_t)((g & 1) * BBYTES);
        #pragma unroll
        for (int o = 0; o < 2; ++o) {
            int lin = tid + o * NTHREADS;
            int r = lin >> 3, gg = lin & 7;
            const void* sp = src + (size_t)(col0 + r) * CDIM + kc + gg * 8;
            cp16(dst + (uint32_t)(r * SROWB + gg * 16), sp);
        }
        cp_commit();
    };

    prefetch(0);   // group0 = A + B chunk 0

    // per-thread rows, norms, streaming state
    float na[4]; int rg[4];
    float m1[4], m2[4]; int i1[4];
    #pragma unroll
    for (int st = 0; st < 4; ++st) {
        rg[st] = row0 + mw * 32 + (st >> 1) * 16 + (lane >> 2) + (st & 1) * 8;
        na[st] = g_norms[b * HW + rg[st]];
        m1[st] = FLT_MAX; m2[st] = FLT_MAX; i1[st] = 0;
    }

    int g = 0;
    for (int jt = 0; jt < NTILES; ++jt) {
        float acc[2][4][4];
        #pragma unroll
        for (int mf = 0; mf < 2; ++mf)
            #pragma unroll
            for (int nf = 0; nf < 4; ++nf)
                #pragma unroll
                for (int e = 0; e < 4; ++e) acc[mf][nf][e] = 0.f;

        for (int c = 0; c < 8; ++c, ++g) {
            __syncthreads();                     // buf (g+1)&1 free on all warps
            if (g + 1 < 8 * NTILES) { prefetch(g + 1); cp_wait<1>(); }
            else                    { cp_wait<0>(); }
            __syncthreads();                     // chunk g visible everywhere

            const uint32_t bb = boff + (uint32_t)((g & 1) * BBYTES);
            const int kcsel = c & 3;
            const bool hiB = (c < 4);
            const uint32_t abase0 = aoff + (uint32_t)((kcsel * 128 + mw * 32 + lrow) * SROWB);
            const uint32_t abase1 = abase0 + (uint32_t)(4 * 128 * SROWB);   // lo region
            const uint32_t bbase  = bb + (uint32_t)((nw * 32 + lrow) * SROWB);

            #pragma unroll
            for (int ks = 0; ks < 4; ++ks) {
                const uint32_t kb = (uint32_t)(ks * 32 + lkb);   // bytes along k
                uint32_t bf[2][4];
                ldsm_x4(bf[0], bbase + kb);
                ldsm_x4(bf[1], bbase + 16 * SROWB + kb);

                uint32_t af[2][4];
                ldsm_x4(af[0], abase0 + kb);                     // A = hi
                ldsm_x4(af[1], abase0 + 16 * SROWB + kb);
                #pragma unroll
                for (int mf = 0; mf < 2; ++mf)
                    #pragma unroll
                    for (int nf = 0; nf < 4; ++nf)
                        MMA16816(acc[mf][nf], af[mf],
                                 bf[nf >> 1][nf & 1], bf[nf >> 1][(nf & 1) + 2]);

                if (hiB) {                                        // A = lo (lo*hi term)
                    uint32_t al[2][4];
                    ldsm_x4(al[0], abase1 + kb);
                    ldsm_x4(al[1], abase1 + 16 * SROWB + kb);
                    #pragma unroll
                    for (int mf = 0; mf < 2; ++mf)
                        #pragma unroll
                        for (int nf = 0; nf < 4; ++nf)
                            MMA16816(acc[mf][nf], al[mf],
                                     bf[nf >> 1][nf & 1], bf[nf >> 1][(nf & 1) + 2]);
                }
            }
        }

        // ---- epilogue: distance + streaming top-2 (registers only) ----
        const int col0 = jt * BN;
        const float* nbp = g_norms + b * HW + col0 + nw * 32 + (lane & 3) * 2;
        #pragma unroll
        for (int nf = 0; nf < 4; ++nf) {
            float2 nb = *(const float2*)(nbp + nf * 8);
            #pragma unroll
            for (int mf = 0; mf < 2; ++mf)
                #pragma unroll
                for (int e = 0; e < 4; ++e) {
                    int st  = mf * 2 + (e >> 1);
                    int cix = col0 + nw * 32 + nf * 8 + (lane & 3) * 2 + (e & 1);
                    float D = na[st] + ((e & 1) ? nb.y : nb.x) - 2.f * acc[mf][nf][e];
                    if (cix != rg[st]) {
                        if (D < m1[st]) { m2[st] = m1[st]; m1[st] = D; i1[st] = cix; }
                        else if (D < m2[st]) { m2[st] = D; }
                    }
                }
        }
    }

    // ---- quad reduce (lanes sharing rows), then cross-warp via SMEM ----
    #pragma unroll
    for (int st = 0; st < 4; ++st) {
        #pragma unroll
        for (int off = 1; off <= 2; off <<= 1) {
            float om1 = __shfl_xor_sync(0xffffffffu, m1[st], off);
            float om2 = __shfl_xor_sync(0xffffffffu, m2[st], off);
            int   oi1 = __shfl_xor_sync(0xffffffffu, i1[st], off);
            if (om1 < m1[st]) { m2[st] = fminf(m1[st], om2); m1[st] = om1; i1[st] = oi1; }
            else              { m2[st] = fminf(m2[st], om1); }
        }
    }
    __syncthreads();                          // done with compute SMEM
    float* sm1 = (float*)smem;                // [4 nw][128]
    float* sm2 = sm1 + 512;
    int*   si1 = (int*)(sm2 + 512);
    if ((lane & 3) == 0) {
        #pragma unroll
        for (int st = 0; st < 4; ++st) {
            int rowl = mw * 32 + (st >> 1) * 16 + (lane >> 2) + (st & 1) * 8;
            sm1[nw * 128 + rowl] = m1[st];
            sm2[nw * 128 + rowl] = m2[st];
            si1[nw * 128 + rowl] = i1[st];
        }
    }
    __syncthreads();
    if (tid < 128) {
        float M1 = FLT_MAX, M2 = FLT_MAX; int I1 = 0;
        #pragma unroll
        for (int q = 0; q < 4; ++q) {
            float a1 = sm1[q * 128 + tid], a2 = sm2[q * 128 + tid];
            int   ai = si1[q * 128 + tid];
            if (a1 < M1) { M2 = fminf(M1, a2); M1 = a1; I1 = ai; }
            else         { M2 = fminf(M2, a1); }
        }
        float d1 = sqrtf(fmaxf(M1, 0.f) + EPSQ);
        float d2 = sqrtf(fmaxf(M2, 0.f) + EPSQ);
        float e  = expf(d1);
        float pred = (d1 / d2 < TLC) ? 2.f / (1.f + e) : 2.f / (1.f + LC * e);
        int r = row0 + tid;
        out[(size_t)b * HW + r] = pred;
        if (out_size >= 2 * BATCH * HW)
            out[(size_t)BATCH * HW + (size_t)b * HW + r] = (float)I1;
    }
}

// ---------------------------------------------------------------------------
extern "C" void kernel_launch(void* const* d_in, const int* in_sizes, int n_in,
                              void* d_out, int out_size) {
    const float* x   = (const float*)d_in[0];
    float*       out = (float*)d_out;

    convert_kernel<<<(BATCH * HW * CDIM / 4) / 256, 256>>>(x);
    norms_kernel<<<(BATCH * HW * 32 + 255) / 256, 256>>>(x);

    cudaFuncSetAttribute(fcm_mma_kernel,
                         cudaFuncAttributeMaxDynamicSharedMemorySize, TOTSMEM);
    dim3 grid(HW / BM, BATCH);
    fcm_mma_kernel<<<grid, NTHREADS, TOTSMEM>>>(out, out_size);
}

// round 4
// speedup vs baseline: 5.0965x; 1.7055x over previous
#include <cuda_runtime.h>
#include <cuda_bf16.h>
#include <cstdint>
#include <float.h>
#include <math.h>

#define BATCH 4
#define HW    4096
#define CDIM  256
#define NSTRIP 32                 // 4096/128 strips per batch
#define NPAIR  528                // 32*33/2 upper-tri tile pairs
#define NTHREADS 512
#define EPSQ  1e-9f
#define TLC   0.6f
#define LC    2.0f
#define SROWB 144                 // padded SMEM row stride (128B data + 16B pad)
#define TENB  (128 * SROWB)       // one 128x64 bf16 tensor chunk: 18432 B
#define STAGEB (4 * TENB)         // A-hi, A-lo, B-hi, B-lo: 73728 B
#define TOTSMEM (2 * STAGEB)      // double buffered: 147456 B

// static device scratch (no allocs in kernel_launch)
__device__ __nv_bfloat16 g_xhi[BATCH * HW * CDIM];
__device__ __nv_bfloat16 g_xlo[BATCH * HW * CDIM];
__device__ float         g_norms[BATCH * HW];
// per-(batch,strip,slot) partial top-2/argmin: slot = source strip block
__device__ float g_pm1[BATCH * NSTRIP * NSTRIP * 128];
__device__ float g_pm2[BATCH * NSTRIP * NSTRIP * 128];
__device__ int   g_pi1[BATCH * NSTRIP * NSTRIP * 128];

// ---------------------------------------------------------------------------
__device__ __forceinline__ uint32_t smem_u32(const void* p) {
    uint32_t a;
    asm("{ .reg .u64 t; cvta.to.shared.u64 t, %1; cvt.u32.u64 %0, t; }"
        : "=r"(a) : "l"(p));
    return a;
}
__device__ __forceinline__ void cp16(uint32_t dst, const void* src) {
    asm volatile("cp.async.cg.shared.global [%0], [%1], 16;" :: "r"(dst), "l"(src));
}
__device__ __forceinline__ void cp_commit() {
    asm volatile("cp.async.commit_group;" ::: "memory");
}
template <int N> __device__ __forceinline__ void cp_wait() {
    asm volatile("cp.async.wait_group %0;" :: "n"(N) : "memory");
}
__device__ __forceinline__ void ldsm_x4(uint32_t (&r)[4], uint32_t addr) {
    asm volatile("ldmatrix.sync.aligned.m8n8.x4.shared.b16 {%0,%1,%2,%3}, [%4];"
                 : "=r"(r[0]), "=r"(r[1]), "=r"(r[2]), "=r"(r[3]) : "r"(addr));
}
#define MMA16816(d, a, b0_, b1_)                                                 \
    asm volatile("mma.sync.aligned.m16n8k16.row.col.f32.bf16.bf16.f32 "          \
                 "{%0,%1,%2,%3}, {%4,%5,%6,%7}, {%8,%9}, {%0,%1,%2,%3};"         \
                 : "+f"((d)[0]), "+f"((d)[1]), "+f"((d)[2]), "+f"((d)[3])        \
                 : "r"((a)[0]), "r"((a)[1]), "r"((a)[2]), "r"((a)[3]),           \
                   "r"(b0_), "r"(b1_))

// ---------------------------------------------------------------------------
__global__ void convert_kernel(const float* __restrict__ x) {
    int i = blockIdx.x * blockDim.x + threadIdx.x;
    float4 v = ((const float4*)x)[i];
    __nv_bfloat16 h0 = __float2bfloat16(v.x), h1 = __float2bfloat16(v.y);
    __nv_bfloat16 h2 = __float2bfloat16(v.z), h3 = __float2bfloat16(v.w);
    __nv_bfloat16 l0 = __float2bfloat16(v.x - __bfloat162float(h0));
    __nv_bfloat16 l1 = __float2bfloat16(v.y - __bfloat162float(h1));
    __nv_bfloat16 l2 = __float2bfloat16(v.z - __bfloat162float(h2));
    __nv_bfloat16 l3 = __float2bfloat16(v.w - __bfloat162float(h3));
    ((__nv_bfloat162*)g_xhi)[2 * i + 0] = __nv_bfloat162(h0, h1);
    ((__nv_bfloat162*)g_xhi)[2 * i + 1] = __nv_bfloat162(h2, h3);
    ((__nv_bfloat162*)g_xlo)[2 * i + 0] = __nv_bfloat162(l0, l1);
    ((__nv_bfloat162*)g_xlo)[2 * i + 1] = __nv_bfloat162(l2, l3);
}

__global__ void norms_kernel(const float* __restrict__ x) {
    int warp = (blockIdx.x * blockDim.x + threadIdx.x) >> 5;
    int lane = threadIdx.x & 31;
    if (warp >= BATCH * HW) return;
    const float4* row = (const float4*)(x + (size_t)warp * CDIM);
    float s = 0.f;
    #pragma unroll
    for (int k = lane; k < CDIM / 4; k += 32) {
        float4 v = row[k];
        s += v.x * v.x + v.y * v.y + v.z * v.z + v.w * v.w;
    }
    #pragma unroll
    for (int o = 16; o; o >>= 1) s += __shfl_xor_sync(0xffffffffu, s, o);
    if (lane == 0) g_norms[warp] = s;
}

// ---------------------------------------------------------------------------
// Tile-pair kernel: CTA = one upper-triangular 128x128 tile pair (i,j).
// Gram = Ahi*Bhi + Alo*Bhi + Ahi*Blo; emits row-side partial (strip i) and
// column-side partial (strip j, skipped when i==j).
// ---------------------------------------------------------------------------
__global__ __launch_bounds__(NTHREADS, 1)
void fcm_pair_kernel() {
    extern __shared__ __align__(16) char smem[];
    const uint32_t sbase = smem_u32(smem);

    const int tid  = threadIdx.x;
    const int lane = tid & 31;
    const int w    = tid >> 5;
    const int mw   = w >> 2;
    const int nw   = w & 3;
    const int b    = blockIdx.y;

    // decode pair index -> (i, j), i<=j ; base(i) = i*(65-i)/2
    int p = blockIdx.x;
    int i = (int)((65.0f - sqrtf(4225.0f - 8.0f * (float)p)) * 0.5f);
    while ((i + 1) * (65 - (i + 1)) / 2 <= p) ++i;
    while (i * (65 - i) / 2 > p) --i;
    const int j = i + (p - i * (65 - i) / 2);
    const int row0 = i * 128, col0 = j * 128;
    const bool diag = (i == j);

    const __nv_bfloat16* xhi = g_xhi + (size_t)b * HW * CDIM;
    const __nv_bfloat16* xlo = g_xlo + (size_t)b * HW * CDIM;

    const int lrow = ((lane >> 3) & 1) * 8 + (lane & 7);
    const int lkb  = (lane >> 4) * 16;

    // stage chunk kc (64 k-values) of A-hi, A-lo, B-hi, B-lo into buffer kc&1
    auto stage = [&](int kc) {
        const uint32_t dst = sbase + (uint32_t)((kc & 1) * STAGEB);
        const __nv_bfloat16* srcs[4] = {
            xhi + (size_t)row0 * CDIM, xlo + (size_t)row0 * CDIM,
            xhi + (size_t)col0 * CDIM, xlo + (size_t)col0 * CDIM };
        #pragma unroll
        for (int t = 0; t < 4; ++t) {
            #pragma unroll
            for (int o = 0; o < 2; ++o) {
                int lin = tid + o * NTHREADS;       // 0..1023
                int r = lin >> 3, gg = lin & 7;
                const void* sp = srcs[t] + (size_t)r * CDIM + kc * 64 + gg * 8;
                cp16(dst + (uint32_t)(t * TENB + r * SROWB + gg * 16), sp);
            }
        }
        cp_commit();
    };

    stage(0);

    float na[4]; int rg[4];
    #pragma unroll
    for (int st = 0; st < 4; ++st) {
        rg[st] = row0 + mw * 32 + (st >> 1) * 16 + (lane >> 2) + (st & 1) * 8;
        na[st] = g_norms[b * HW + rg[st]];
    }

    float acc[2][4][4];
    #pragma unroll
    for (int mf = 0; mf < 2; ++mf)
        #pragma unroll
        for (int nf = 0; nf < 4; ++nf)
            #pragma unroll
            for (int e = 0; e < 4; ++e) acc[mf][nf][e] = 0.f;

    for (int kc = 0; kc < 4; ++kc) {
        cp_wait<0>();
        __syncthreads();
        if (kc < 3) stage(kc + 1);

        const uint32_t bb    = sbase + (uint32_t)((kc & 1) * STAGEB);
        const uint32_t ahib  = bb + (uint32_t)((mw * 32 + lrow) * SROWB);
        const uint32_t alob  = ahib + TENB;
        const uint32_t bhib  = bb + (uint32_t)(2 * TENB + (nw * 32 + lrow) * SROWB);
        const uint32_t blob  = bhib + TENB;

        #pragma unroll
        for (int ks = 0; ks < 4; ++ks) {
            const uint32_t kb = (uint32_t)(ks * 32 + lkb);

            uint32_t ah[2][4], bh[2][4];
            ldsm_x4(ah[0], ahib + kb);
            ldsm_x4(ah[1], ahib + 16 * SROWB + kb);
            ldsm_x4(bh[0], bhib + kb);
            ldsm_x4(bh[1], bhib + 16 * SROWB + kb);
            #pragma unroll
            for (int mf = 0; mf < 2; ++mf)
                #pragma unroll
                for (int nf = 0; nf < 4; ++nf)
                    MMA16816(acc[mf][nf], ah[mf],
                             bh[nf >> 1][nf & 1], bh[nf >> 1][(nf & 1) + 2]);

            {   // lo-A x hi-B
                uint32_t al[2][4];
                ldsm_x4(al[0], alob + kb);
                ldsm_x4(al[1], alob + 16 * SROWB + kb);
                #pragma unroll
                for (int mf = 0; mf < 2; ++mf)
                    #pragma unroll
                    for (int nf = 0; nf < 4; ++nf)
                        MMA16816(acc[mf][nf], al[mf],
                                 bh[nf >> 1][nf & 1], bh[nf >> 1][(nf & 1) + 2]);
            }
            {   // hi-A x lo-B (A-hi frags reused)
                uint32_t bl[2][4];
                ldsm_x4(bl[0], blob + kb);
                ldsm_x4(bl[1], blob + 16 * SROWB + kb);
                #pragma unroll
                for (int mf = 0; mf < 2; ++mf)
                    #pragma unroll
                    for (int nf = 0; nf < 4; ++nf)
                        MMA16816(acc[mf][nf], ah[mf],
                                 bl[nf >> 1][nf & 1], bl[nf >> 1][(nf & 1) + 2]);
            }
        }
    }

    // ---- convert acc -> squared distance in place ----
    const float* nbp = g_norms + b * HW + col0 + nw * 32 + (lane & 3) * 2;
    #pragma unroll
    for (int nf = 0; nf < 4; ++nf) {
        float2 nb = *(const float2*)(nbp + nf * 8);
        #pragma unroll
        for (int mf = 0; mf < 2; ++mf)
            #pragma unroll
            for (int e = 0; e < 4; ++e) {
                int st = mf * 2 + (e >> 1);
                acc[mf][nf][e] = na[st] + ((e & 1) ? nb.y : nb.x)
                               - 2.f * acc[mf][nf][e];
            }
    }

    // ---- row-side top-2/argmin over this tile's 128 cols ----
    float m1r[4], m2r[4]; int i1r[4];
    #pragma unroll
    for (int st = 0; st < 4; ++st) { m1r[st] = FLT_MAX; m2r[st] = FLT_MAX; i1r[st] = 0; }
    #pragma unroll
    for (int nf = 0; nf < 4; ++nf)
        #pragma unroll
        for (int mf = 0; mf < 2; ++mf)
            #pragma unroll
            for (int e = 0; e < 4; ++e) {
                int st  = mf * 2 + (e >> 1);
                int cix = col0 + nw * 32 + nf * 8 + (lane & 3) * 2 + (e & 1);
                float D = acc[mf][nf][e];
                if (cix != rg[st]) {
                    if (D < m1r[st]) { m2r[st] = m1r[st]; m1r[st] = D; i1r[st] = cix; }
                    else if (D < m2r[st]) { m2r[st] = D; }
                }
            }
    #pragma unroll
    for (int st = 0; st < 4; ++st)
        #pragma unroll
        for (int off = 1; off <= 2; off <<= 1) {
            float om1 = __shfl_xor_sync(0xffffffffu, m1r[st], off);
            float om2 = __shfl_xor_sync(0xffffffffu, m2r[st], off);
            int   oi1 = __shfl_xor_sync(0xffffffffu, i1r[st], off);
            if (om1 < m1r[st]) { m2r[st] = fminf(m1r[st], om2); m1r[st] = om1; i1r[st] = oi1; }
            else               { m2r[st] = fminf(m2r[st], om1); }
        }

    // ---- col-side top-2/argmin over this tile's 128 rows (skip diagonal) ----
    float m1c[8], m2c[8]; int i1c[8];
    if (!diag) {
        #pragma unroll
        for (int cs = 0; cs < 8; ++cs) { m1c[cs] = FLT_MAX; m2c[cs] = FLT_MAX; i1c[cs] = 0; }
        #pragma unroll
        for (int nf = 0; nf < 4; ++nf)
            #pragma unroll
            for (int e = 0; e < 4; ++e) {
                int cs = nf * 2 + (e & 1);
                #pragma unroll
                for (int mf = 0; mf < 2; ++mf) {
                    int st = mf * 2 + (e >> 1);
                    float D = acc[mf][nf][e];
                    int   r = rg[st];
                    if (D < m1c[cs]) { m2c[cs] = m1c[cs]; m1c[cs] = D; i1c[cs] = r; }
                    else if (D < m2c[cs]) { m2c[cs] = D; }
                }
            }
        #pragma unroll
        for (int cs = 0; cs < 8; ++cs)
            #pragma unroll
            for (int off = 4; off <= 16; off <<= 1) {
                float om1 = __shfl_xor_sync(0xffffffffu, m1c[cs], off);
                float om2 = __shfl_xor_sync(0xffffffffu, m2c[cs], off);
                int   oi1 = __shfl_xor_sync(0xffffffffu, i1c[cs], off);
                if (om1 < m1c[cs]) { m2c[cs] = fminf(m1c[cs], om2); m1c[cs] = om1; i1c[cs] = oi1; }
                else               { m2c[cs] = fminf(m2c[cs], om1); }
            }
    }

    // ---- cross-warp merge via SMEM, write partials ----
    __syncthreads();                      // mainloop smem reads complete
    float* sr1 = (float*)smem;            // row area [4 nw][128]
    float* sr2 = sr1 + 512;
    int*   sri = (int*)(sr2 + 512);
    float* sc1 = (float*)(sri + 512);     // col area [4 mw][128]
    float* sc2 = sc1 + 512;
    int*   sci = (int*)(sc2 + 512);

    if ((lane & 3) == 0) {
        #pragma unroll
        for (int st = 0; st < 4; ++st) {
            int rowl = mw * 32 + (st >> 1) * 16 + (lane >> 2) + (st & 1) * 8;
            sr1[nw * 128 + rowl] = m1r[st];
            sr2[nw * 128 + rowl] = m2r[st];
            sri[nw * 128 + rowl] = i1r[st];
        }
    }
    if (!diag && lane < 4) {
        #pragma unroll
        for (int cs = 0; cs < 8; ++cs) {
            int coll = nw * 32 + (cs >> 1) * 8 + lane * 2 + (cs & 1);
            sc1[mw * 128 + coll] = m1c[cs];
            sc2[mw * 128 + coll] = m2c[cs];
            sci[mw * 128 + coll] = i1c[cs];
        }
    }
    __syncthreads();

    if (tid < 128) {
        {   // strip i, slot j  (row-side)
            float M1 = FLT_MAX, M2 = FLT_MAX; int I1 = 0;
            #pragma unroll
            for (int q = 0; q < 4; ++q) {
                float a1 = sr1[q * 128 + tid], a2 = sr2[q * 128 + tid];
                int   ai = sri[q * 128 + tid];
                if (a1 < M1) { M2 = fminf(M1, a2); M1 = a1; I1 = ai; }
                else         { M2 = fminf(M2, a1); }
            }
            int o = ((b * NSTRIP + i) * NSTRIP + j) * 128 + tid;
            g_pm1[o] = M1; g_pm2[o] = M2; g_pi1[o] = I1;
        }
        if (!diag) {   // strip j, slot i  (col-side)
            float M1 = FLT_MAX, M2 = FLT_MAX; int I1 = 0;
            #pragma unroll
            for (int q = 0; q < 4; ++q) {
                float a1 = sc1[q * 128 + tid], a2 = sc2[q * 128 + tid];
                int   ai = sci[q * 128 + tid];
                if (a1 < M1) { M2 = fminf(M1, a2); M1 = a1; I1 = ai; }
                else         { M2 = fminf(M2, a1); }
            }
            int o = ((b * NSTRIP + j) * NSTRIP + i) * 128 + tid;
            g_pm1[o] = M1; g_pm2[o] = M2; g_pi1[o] = I1;
        }
    }
}

// ---------------------------------------------------------------------------
// Merge partials (ascending slot order == ascending global index blocks,
// preserving lowest-index tie-break) + final prediction math.
// ---------------------------------------------------------------------------
__global__ void merge_kernel(float* __restrict__ out, int out_size) {
    int idx = blockIdx.x * blockDim.x + threadIdx.x;   // 0..16383
    int b  = idx >> 12;
    int rl = idx & 4095;
    int s  = rl >> 7;
    int r  = rl & 127;
    int base = ((b * NSTRIP + s) * NSTRIP) * 128 + r;
    float M1 = FLT_MAX, M2 = FLT_MAX; int I1 = 0;
    for (int t = 0; t < NSTRIP; ++t) {
        float a1 = g_pm1[base + t * 128];
        float a2 = g_pm2[base + t * 128];
        int   ai = g_pi1[base + t * 128];
        if (a1 < M1) { M2 = fminf(M1, a2); M1 = a1; I1 = ai; }
        else         { M2 = fminf(M2, a1); }
    }
    float d1 = sqrtf(fmaxf(M1, 0.f) + EPSQ);
    float d2 = sqrtf(fmaxf(M2, 0.f) + EPSQ);
    float e  = expf(d1);
    float pred = (d1 / d2 < TLC) ? 2.f / (1.f + e) : 2.f / (1.f + LC * e);
    out[(size_t)b * HW + rl] = pred;
    if (out_size >= 2 * BATCH * HW)
        out[(size_t)BATCH * HW + (size_t)b * HW + rl] = (float)I1;
}

// ---------------------------------------------------------------------------
extern "C" void kernel_launch(void* const* d_in, const int* in_sizes, int n_in,
                              void* d_out, int out_size) {
    const float* x   = (const float*)d_in[0];
    float*       out = (float*)d_out;

    convert_kernel<<<(BATCH * HW * CDIM / 4) / 256, 256>>>(x);
    norms_kernel<<<(BATCH * HW * 32 + 255) / 256, 256>>>(x);

    cudaFuncSetAttribute(fcm_pair_kernel,
                         cudaFuncAttributeMaxDynamicSharedMemorySize, TOTSMEM);
    dim3 grid(NPAIR, BATCH);
    fcm_pair_kernel<<<grid, NTHREADS, TOTSMEM>>>();

    merge_kernel<<<BATCH * HW / 256, 256>>>(out, out_size);
}